// round 3
// baseline (speedup 1.0000x reference)
#include <cuda_runtime.h>
#include <cstdint>
#include <math.h>

// ---------------------------------------------------------------------------
// Problem constants
// ---------------------------------------------------------------------------
#define BB   128
#define TT   100
#define HIDN 512
#define G3   1536

#define P1   576      // 24*24
#define P2   81       // 9*9
#define P3   16       // 4*4
#define K1P  80       // conv1 K padded (3*5*5=75 -> 80)
#define K1R  75
#define K23  576      // 64*3*3

#define C1_M (BB*P1)  // 73728
#define C2_M (BB*P2)  // 10368
#define C3_M (BB*P3)  // 2048

// GRU tiling
#define GMB  32       // batch tile
#define GJT  16       // hidden-col tile
#define GNC  128      // CTAs = (128/32)*(512/16)
#define GTH  256      // threads (8 warps)
#define HS_STRIDE 516
#define WS_STRIDE 516

// ---------------------------------------------------------------------------
// Device scratch (no allocations allowed -> __device__ globals)
// ---------------------------------------------------------------------------
__device__ float g_col1[(size_t)C1_M * K1P];
__device__ float g_x1  [(size_t)BB * 64 * P1];
__device__ float g_col2[(size_t)C2_M * K23];
__device__ float g_x2  [(size_t)BB * 64 * P2];
__device__ float g_col3[(size_t)C3_M * K23];
__device__ float g_flat[(size_t)BB * 1024];
__device__ float g_fc1 [(size_t)BB * 1024];
__device__ float g_fc2 [(size_t)BB * 512];
__device__ __align__(16) float g_h[2][(size_t)BB * HIDN];
__device__ float g_gi  [(size_t)TT * BB * G3];
__device__ unsigned g_bar_count;
__device__ volatile unsigned g_bar_gen;

// ---------------------------------------------------------------------------
// Helpers
// ---------------------------------------------------------------------------
__device__ __forceinline__ float tf32f(float x) {
    unsigned u;
    asm("cvt.rna.tf32.f32 %0, %1;" : "=r"(u) : "f"(x));
    return __uint_as_float(u);
}

__device__ __forceinline__ void mma8(float* c,
                                     float a0, float a1, float a2, float a3,
                                     float b0, float b1) {
    unsigned A0 = __float_as_uint(a0), A1 = __float_as_uint(a1);
    unsigned A2 = __float_as_uint(a2), A3 = __float_as_uint(a3);
    unsigned B0 = __float_as_uint(b0), B1 = __float_as_uint(b1);
    asm volatile(
        "mma.sync.aligned.m16n8k8.row.col.f32.tf32.tf32.f32 "
        "{%0,%1,%2,%3}, {%4,%5,%6,%7}, {%8,%9}, {%0,%1,%2,%3};"
        : "+f"(c[0]), "+f"(c[1]), "+f"(c[2]), "+f"(c[3])
        : "r"(A0), "r"(A1), "r"(A2), "r"(A3), "r"(B0), "r"(B1));
}

// ---------------------------------------------------------------------------
// Barrier init
// ---------------------------------------------------------------------------
__global__ void init_bar_k() {
    g_bar_count = 0u;
    g_bar_gen = 0u;
}

// ---------------------------------------------------------------------------
// im2col kernels
// ---------------------------------------------------------------------------
__global__ void im2col1_k(const float* __restrict__ img) {
    int idx = blockIdx.x * blockDim.x + threadIdx.x;
    if (idx >= C1_M * K1P) return;
    int row = idx / K1P, k = idx % K1P;
    float v = 0.f;
    if (k < K1R) {
        int b = row / P1, pix = row % P1;
        int oy = pix / 24, ox = pix % 24;
        int ci = k / 25, rem = k % 25;
        int ky = rem / 5, kx = rem % 5;
        int iy = oy * 3 - 2 + ky;
        int ix = ox * 3 - 2 + kx;
        if (iy >= 0 && iy < 72 && ix >= 0 && ix < 72)
            v = img[((size_t)(b * 3 + ci) * 72 + iy) * 72 + ix];
    }
    g_col1[idx] = v;
}

__global__ void im2col2_k() {
    int idx = blockIdx.x * blockDim.x + threadIdx.x;
    if (idx >= C2_M * K23) return;
    int row = idx / K23, k = idx % K23;
    int b = row / P2, pix = row % P2;
    int oy = pix / 9, ox = pix % 9;
    int ci = k / 9, rem = k % 9;
    int ky = rem / 3, kx = rem % 3;
    int iy = oy * 3 - 2 + ky;
    int ix = ox * 3 - 2 + kx;
    float v = 0.f;
    if (iy >= 0 && iy < 24 && ix >= 0 && ix < 24)
        v = g_x1[((size_t)(b * 64 + ci) * 24 + iy) * 24 + ix];
    g_col2[idx] = v;
}

__global__ void im2col3_k() {
    int idx = blockIdx.x * blockDim.x + threadIdx.x;
    if (idx >= C3_M * K23) return;
    int row = idx / K23, k = idx % K23;
    int b = row / P3, pix = row % P3;
    int oy = pix / 4, ox = pix % 4;
    int ci = k / 9, rem = k % 9;
    int ky = rem / 3, kx = rem % 3;
    int iy = oy * 3 - 2 + ky;
    int ix = ox * 3 - 2 + kx;
    float v = 0.f;
    if (iy >= 0 && iy < 9 && ix >= 0 && ix < 9)
        v = g_x2[((size_t)(b * 64 + ci) * 9 + iy) * 9 + ix];
    g_col3[idx] = v;
}

// ---------------------------------------------------------------------------
// Generic tf32 tensor-core GEMM:  C[M,N] = A[M,K] * W[N,K]^T + bias
//   A row-major (lda), W row-major [N, ldw] with zero-extension beyond KW.
//   M % 128 == 0, Ntot % 64 == 0, K % 16 == 0 (all shapes here satisfy this).
//   mode 0: C[m*Ntot + n]
//   mode 1: m = b*pix + p  ->  C[(b*Ntot + n)*pix + p]   (NCHW conv output)
// ---------------------------------------------------------------------------
__global__ void gemm_k(const float* __restrict__ A, int lda,
                       const float* __restrict__ W, int ldw, int KW,
                       const float* __restrict__ bias,
                       float* __restrict__ C,
                       int K, int Ntot, int relu, int mode, int pix) {
    __shared__ float As[128 * 20];
    __shared__ float Bs[64 * 20];

    int tid = threadIdx.x;
    int warp = tid >> 5, lane = tid & 31;
    int wm = warp >> 1;        // 0..3 : 32 rows each
    int wn = warp & 1;         // 0..1 : 32 cols each
    int m0 = blockIdx.x * 128;
    int n0 = blockIdx.y * 64;

    float acc[2][4][4];
#pragma unroll
    for (int a = 0; a < 2; a++)
#pragma unroll
        for (int b = 0; b < 4; b++)
#pragma unroll
            for (int c = 0; c < 4; c++) acc[a][b][c] = 0.f;

    for (int k0 = 0; k0 < K; k0 += 16) {
        __syncthreads();
        // load A tile 128x16
#pragma unroll
        for (int i = 0; i < 8; i++) {
            int e = i * 256 + tid;
            int m = e >> 4, k = e & 15;
            As[m * 20 + k] = tf32f(A[(size_t)(m0 + m) * lda + k0 + k]);
        }
        // load W tile 64x16 (with K guard for conv1's 75-wide weights)
#pragma unroll
        for (int i = 0; i < 4; i++) {
            int e = i * 256 + tid;
            int n = e >> 4, k = e & 15;
            float v = (k0 + k < KW) ? W[(size_t)(n0 + n) * ldw + k0 + k] : 0.f;
            Bs[n * 20 + k] = tf32f(v);
        }
        __syncthreads();

#pragma unroll
        for (int kk = 0; kk < 2; kk++) {
            int kb = kk * 8;
#pragma unroll
            for (int mt = 0; mt < 2; mt++) {
                int r = wm * 32 + mt * 16 + (lane >> 2);
                int c = kb + (lane & 3);
                float a0 = As[r * 20 + c];
                float a1 = As[(r + 8) * 20 + c];
                float a2 = As[r * 20 + c + 4];
                float a3 = As[(r + 8) * 20 + c + 4];
#pragma unroll
                for (int nt = 0; nt < 4; nt++) {
                    int n = wn * 32 + nt * 8 + (lane >> 2);
                    float b0 = Bs[n * 20 + kb + (lane & 3)];
                    float b1 = Bs[n * 20 + kb + 4 + (lane & 3)];
                    mma8(acc[mt][nt], a0, a1, a2, a3, b0, b1);
                }
            }
        }
    }

    // epilogue
#pragma unroll
    for (int mt = 0; mt < 2; mt++) {
#pragma unroll
        for (int nt = 0; nt < 4; nt++) {
            int r = m0 + wm * 32 + mt * 16 + (lane >> 2);
            int cc = n0 + wn * 32 + nt * 8 + 2 * (lane & 3);
#pragma unroll
            for (int q = 0; q < 4; q++) {
                int rr = r + (q >> 1) * 8;
                int cn = cc + (q & 1);
                float v = acc[mt][nt][q] + bias[cn];
                if (relu) v = fmaxf(v, 0.f);
                if (mode == 0) {
                    C[(size_t)rr * Ntot + cn] = v;
                } else {
                    int b = rr / pix, p = rr % pix;
                    C[((size_t)b * Ntot + cn) * pix + p] = v;
                }
            }
        }
    }
}

// ---------------------------------------------------------------------------
// gi precompute: gi[t][b][g] = actions[b][t][:] . w_ih[g][:] + b_ih[g]
// ---------------------------------------------------------------------------
__global__ void gi_k(const float* __restrict__ actions,
                     const float* __restrict__ w_ih,
                     const float* __restrict__ b_ih) {
    int idx = blockIdx.x * blockDim.x + threadIdx.x;
    if (idx >= TT * BB * G3) return;
    int g = idx % G3;
    int tb = idx / G3;
    int b = tb % BB, t = tb / BB;
    float a0 = actions[((size_t)b * TT + t) * 2 + 0];
    float a1 = actions[((size_t)b * TT + t) * 2 + 1];
    g_gi[idx] = a0 * w_ih[g * 2] + a1 * w_ih[g * 2 + 1] + b_ih[g];
}

// ---------------------------------------------------------------------------
// Persistent GRU kernel. 128 CTAs x 256 threads, grid barrier per step.
// CTA (ib, jg): batch rows [ib*32, +32), hidden cols [jg*16, +16).
// Per step:  gh[b, {j,512+j,1024+j}] = h . w_hh_rows^T  (tf32 mma, smem weights)
//            then gates fused in-CTA, one grid barrier.
// ---------------------------------------------------------------------------
__device__ __forceinline__ void grid_barrier(unsigned target) {
    __syncthreads();
    __threadfence();
    if (threadIdx.x == 0) {
        unsigned a = atomicAdd(&g_bar_count, 1u);
        if (a == GNC - 1) {
            g_bar_count = 0u;
            __threadfence();
            atomicAdd((unsigned*)&g_bar_gen, 1u);
        } else {
            while (g_bar_gen < target) { }
        }
    }
    __syncthreads();
}

__global__ void __launch_bounds__(GTH, 1)
gru_k(const float* __restrict__ gi,
      const float* __restrict__ w_hh,
      const float* __restrict__ b_hh,
      float* __restrict__ out,
      float* __restrict__ hT) {
    extern __shared__ float sm[];
    float* Hs = sm;                              // [32][516]
    float* Ws = sm + 32 * HS_STRIDE;             // [48][516]  (gate-major rows)
    float* Gs = Ws + 48 * WS_STRIDE;             // [32][48]

    int tid = threadIdx.x;
    int warp = tid >> 5, lane = tid & 31;
    int wm = warp & 1;                 // batch half (16 rows)
    int wn = warp >> 1;                // 0..3 -> n8-subtile lists {0,1},{2,3},{4},{5}
    int nsub = (wn < 2) ? 2 : 1;
    int sub0 = (wn < 2) ? wn * 2 : wn + 2;

    int cta = blockIdx.x;
    int ib = cta >> 5;                 // 0..3
    int jg = cta & 31;                 // 0..31
    int j0 = jg * GJT;

    // Load w_hh slice once: rows {j0..j0+15} of gates r,i,n (48 rows x 512)
    for (int e = tid; e < 48 * 512; e += GTH) {
        int rr = e >> 9, k = e & 511;
        int gate = rr >> 4, jj = rr & 15;
        Ws[rr * WS_STRIDE + k] =
            tf32f(w_hh[((size_t)gate * 512 + j0 + jj) * 512 + k]);
    }

    unsigned bar = 0;

    for (int t = 0; t < TT; t++) {
        const float* hcur = g_h[t & 1];
        float* hnxt = g_h[(t + 1) & 1];

        // stage h tile (tf32-rounded) into smem; .cg to dodge stale L1
        {
            const float4* hsrc = reinterpret_cast<const float4*>(hcur);
            for (int e = tid; e < 32 * 128; e += GTH) {
                int r = e >> 7, c4 = e & 127;
                float4 v = __ldcg(hsrc + (size_t)(ib * 32 + r) * 128 + c4);
                int base = r * HS_STRIDE + c4 * 4;
                Hs[base + 0] = tf32f(v.x);
                Hs[base + 1] = tf32f(v.y);
                Hs[base + 2] = tf32f(v.z);
                Hs[base + 3] = tf32f(v.w);
            }
        }
        __syncthreads();

        float acc[2][4];
#pragma unroll
        for (int a = 0; a < 2; a++)
#pragma unroll
            for (int c = 0; c < 4; c++) acc[a][c] = 0.f;

#pragma unroll 4
        for (int k8 = 0; k8 < 64; k8++) {
            int kb = k8 * 8;
            int r = wm * 16 + (lane >> 2);
            int c = kb + (lane & 3);
            float a0 = Hs[r * HS_STRIDE + c];
            float a1 = Hs[(r + 8) * HS_STRIDE + c];
            float a2 = Hs[r * HS_STRIDE + c + 4];
            float a3 = Hs[(r + 8) * HS_STRIDE + c + 4];
#pragma unroll
            for (int i = 0; i < 2; i++) {
                if (i < nsub) {
                    int n = (sub0 + i) * 8 + (lane >> 2);
                    float b0 = Ws[n * WS_STRIDE + kb + (lane & 3)];
                    float b1 = Ws[n * WS_STRIDE + kb + 4 + (lane & 3)];
                    mma8(acc[i], a0, a1, a2, a3, b0, b1);
                }
            }
        }

        // dump gh fragments to smem for gate fusion
#pragma unroll
        for (int i = 0; i < 2; i++) {
            if (i < nsub) {
                int s = sub0 + i;
                int r = wm * 16 + (lane >> 2);
                int c = s * 8 + 2 * (lane & 3);
                Gs[r * 48 + c]           = acc[i][0];
                Gs[r * 48 + c + 1]       = acc[i][1];
                Gs[(r + 8) * 48 + c]     = acc[i][2];
                Gs[(r + 8) * 48 + c + 1] = acc[i][3];
            }
        }
        __syncthreads();

        // fused gates (exact f32 state update)
        for (int e = tid; e < GMB * GJT; e += GTH) {
            int bl = e >> 4, jj = e & 15;
            int bg = ib * 32 + bl;
            int j = j0 + jj;
            float ghr = Gs[bl * 48 + jj]      + b_hh[j];
            float ghi = Gs[bl * 48 + 16 + jj] + b_hh[512 + j];
            float ghn = Gs[bl * 48 + 32 + jj] + b_hh[1024 + j];
            const float* git = gi + ((size_t)t * BB + bg) * G3;
            float r = 1.f / (1.f + expf(-(git[j] + ghr)));
            float z = 1.f / (1.f + expf(-(git[512 + j] + ghi)));
            float n = tanhf(git[1024 + j] + r * ghn);
            float hv = hcur[(size_t)bg * HIDN + j];
            float hy = n + z * (hv - n);
            hnxt[(size_t)bg * HIDN + j] = hy;
            out[((size_t)bg * TT + t) * HIDN + j] = hy;
            if (t == TT - 1) hT[(size_t)bg * HIDN + j] = hy;
        }

        grid_barrier(++bar);
    }
}

// ---------------------------------------------------------------------------
// Host launch
// ---------------------------------------------------------------------------
extern "C" void kernel_launch(void* const* d_in, const int* in_sizes, int n_in,
                              void* d_out, int out_size) {
    const float* images  = (const float*)d_in[0];
    const float* actions = (const float*)d_in[1];
    const float* cw1 = (const float*)d_in[2];
    const float* cb1 = (const float*)d_in[3];
    const float* cw2 = (const float*)d_in[4];
    const float* cb2 = (const float*)d_in[5];
    const float* cw3 = (const float*)d_in[6];
    const float* cb3 = (const float*)d_in[7];
    const float* fw1 = (const float*)d_in[8];
    const float* fb1 = (const float*)d_in[9];
    const float* fw2 = (const float*)d_in[10];
    const float* fb2 = (const float*)d_in[11];
    const float* fw3 = (const float*)d_in[12];
    const float* fb3 = (const float*)d_in[13];
    const float* w_ih = (const float*)d_in[14];
    const float* w_hh = (const float*)d_in[15];
    const float* b_ih = (const float*)d_in[16];
    const float* b_hh = (const float*)d_in[17];

    float *col1, *col2, *col3, *x1, *x2, *flat, *fc1, *fc2, *hbuf, *gi;
    cudaGetSymbolAddress((void**)&col1, g_col1);
    cudaGetSymbolAddress((void**)&col2, g_col2);
    cudaGetSymbolAddress((void**)&col3, g_col3);
    cudaGetSymbolAddress((void**)&x1,   g_x1);
    cudaGetSymbolAddress((void**)&x2,   g_x2);
    cudaGetSymbolAddress((void**)&flat, g_flat);
    cudaGetSymbolAddress((void**)&fc1,  g_fc1);
    cudaGetSymbolAddress((void**)&fc2,  g_fc2);
    cudaGetSymbolAddress((void**)&hbuf, g_h);
    cudaGetSymbolAddress((void**)&gi,   g_gi);

    const int gru_smem = (32 * HS_STRIDE + 48 * WS_STRIDE + 32 * 48) * 4;
    cudaFuncSetAttribute(gru_k, cudaFuncAttributeMaxDynamicSharedMemorySize,
                         gru_smem);

    init_bar_k<<<1, 1>>>();

    // encoder
    im2col1_k<<<(C1_M * K1P + 255) / 256, 256>>>(images);
    gemm_k<<<dim3(C1_M / 128, 1), 256>>>(col1, K1P, cw1, K1R, K1R, cb1,
                                         x1, K1P, 64, 1, 1, P1);
    im2col2_k<<<(C2_M * K23 + 255) / 256, 256>>>();
    gemm_k<<<dim3(C2_M / 128, 1), 256>>>(col2, K23, cw2, K23, K23, cb2,
                                         x2, K23, 64, 1, 1, P2);
    im2col3_k<<<(C3_M * K23 + 255) / 256, 256>>>();
    gemm_k<<<dim3(C3_M / 128, 1), 256>>>(col3, K23, cw3, K23, K23, cb3,
                                         flat, K23, 64, 1, 1, P3);
    gemm_k<<<dim3(1, 16), 256>>>(flat, 1024, fw1, 1024, 1024, fb1,
                                 fc1, 1024, 1024, 1, 0, 0);
    gemm_k<<<dim3(1, 8), 256>>>(fc1, 1024, fw2, 1024, 1024, fb2,
                                fc2, 1024, 512, 1, 0, 0);
    gemm_k<<<dim3(1, 8), 256>>>(fc2, 512, fw3, 512, 512, fb3,
                                hbuf /* g_h[0] */, 512, 512, 0, 0, 0);

    // GRU input projections
    gi_k<<<(TT * BB * G3 + 255) / 256, 256>>>(actions, w_ih, b_ih);

    // persistent GRU
    float* out = (float*)d_out;
    float* hT = out + (size_t)BB * TT * HIDN;
    gru_k<<<GNC, GTH, gru_smem>>>(gi, w_hh, b_hh, out, hT);
}

// round 4
// speedup vs baseline: 1.4567x; 1.4567x over previous
#include <cuda_runtime.h>
#include <cstdint>
#include <math.h>

// ---------------------------------------------------------------------------
// Problem constants
// ---------------------------------------------------------------------------
#define BB   128
#define TT   100
#define HIDN 512
#define G3   1536

// GRU tiling
#define GMB  32       // batch tile
#define GJT  16       // hidden-col tile
#define GNC  128      // CTAs = (128/32)*(512/16)
#define GTH  256      // threads (8 warps)
#define HS_STRIDE 516
#define WS_STRIDE 516

// ---------------------------------------------------------------------------
// Device scratch (no allocations allowed -> __device__ globals)
// ---------------------------------------------------------------------------
__device__ float g_x1  [(size_t)BB * 64 * 576];   // conv1 out, NCHW
__device__ float g_x2  [(size_t)BB * 64 * 81];    // conv2 out, NCHW
__device__ float g_flat[(size_t)BB * 1024];       // conv3 out == flatten
__device__ float g_fc1 [(size_t)BB * 1024];
__device__ float g_fc2 [(size_t)BB * 512];
__device__ __align__(16) float g_h[2][(size_t)BB * HIDN];
__device__ float g_gi  [(size_t)TT * BB * G3];
__device__ unsigned g_flag[4][32][32];            // [group][cta][pad to 128B]

// ---------------------------------------------------------------------------
// Helpers
// ---------------------------------------------------------------------------
__device__ __forceinline__ float tf32f(float x) {
    unsigned u;
    asm("cvt.rna.tf32.f32 %0, %1;" : "=r"(u) : "f"(x));
    return __uint_as_float(u);
}

__device__ __forceinline__ void mma8(float* c,
                                     float a0, float a1, float a2, float a3,
                                     float b0, float b1) {
    unsigned A0 = __float_as_uint(a0), A1 = __float_as_uint(a1);
    unsigned A2 = __float_as_uint(a2), A3 = __float_as_uint(a3);
    unsigned B0 = __float_as_uint(b0), B1 = __float_as_uint(b1);
    asm volatile(
        "mma.sync.aligned.m16n8k8.row.col.f32.tf32.tf32.f32 "
        "{%0,%1,%2,%3}, {%4,%5,%6,%7}, {%8,%9}, {%0,%1,%2,%3};"
        : "+f"(c[0]), "+f"(c[1]), "+f"(c[2]), "+f"(c[3])
        : "r"(A0), "r"(A1), "r"(A2), "r"(A3), "r"(B0), "r"(B1));
}

// ---------------------------------------------------------------------------
// Fused im2col + tf32 GEMM conv:  out[b, oc, p] = relu(conv(src) + bias)
//   src NCHW [B, CIN, IH, IH]; W [64, KW] row-major (KW = CIN*KS*KS);
//   stride 3, pad 2.  Ntot = 64 (single n-block).  M = B*OW*OW, tiled by 128.
// ---------------------------------------------------------------------------
template<int KTOT, int KW, int CIN, int IH, int KS, int OW>
__global__ void convgemm_k(const float* __restrict__ src,
                           const float* __restrict__ W,
                           const float* __restrict__ bias,
                           float* __restrict__ C) {
    constexpr int PIX = OW * OW;
    __shared__ float As[128 * 20];
    __shared__ float Bs[64 * 20];

    int tid = threadIdx.x;
    int warp = tid >> 5, lane = tid & 31;
    int wm = warp >> 1;        // 0..3 : 32 rows each
    int wn = warp & 1;         // 0..1 : 32 cols each
    int m0 = blockIdx.x * 128;

    float acc[2][4][4];
#pragma unroll
    for (int a = 0; a < 2; a++)
#pragma unroll
        for (int b = 0; b < 4; b++)
#pragma unroll
            for (int c = 0; c < 4; c++) acc[a][b][c] = 0.f;

    for (int k0 = 0; k0 < KTOT; k0 += 16) {
        __syncthreads();
        // A tile 128x16: im2col on the fly
        {
            int kk = tid & 15;
            int k = k0 + kk;
            int ci = 0, ky = 0, kx = 0;
            bool kok = (k < KW);
            if (kok) {
                ci = k / (KS * KS);
                int rem = k % (KS * KS);
                ky = rem / KS; kx = rem % KS;
            }
#pragma unroll
            for (int i = 0; i < 8; i++) {
                int mloc = i * 16 + (tid >> 4);
                int m = m0 + mloc;
                float v = 0.f;
                if (kok) {
                    int b = m / PIX, pix = m % PIX;
                    int oy = pix / OW, ox = pix % OW;
                    int iy = oy * 3 - 2 + ky;
                    int ix = ox * 3 - 2 + kx;
                    if (iy >= 0 && iy < IH && ix >= 0 && ix < IH)
                        v = src[((size_t)(b * CIN + ci) * IH + iy) * IH + ix];
                }
                As[mloc * 20 + kk] = tf32f(v);
            }
        }
        // W tile 64x16
#pragma unroll
        for (int i = 0; i < 4; i++) {
            int e = i * 256 + tid;
            int n = e >> 4, k = e & 15;
            float v = (k0 + k < KW) ? W[(size_t)n * KW + k0 + k] : 0.f;
            Bs[n * 20 + k] = tf32f(v);
        }
        __syncthreads();

#pragma unroll
        for (int kk = 0; kk < 2; kk++) {
            int kb = kk * 8;
#pragma unroll
            for (int mt = 0; mt < 2; mt++) {
                int r = wm * 32 + mt * 16 + (lane >> 2);
                int c = kb + (lane & 3);
                float a0 = As[r * 20 + c];
                float a1 = As[(r + 8) * 20 + c];
                float a2 = As[r * 20 + c + 4];
                float a3 = As[(r + 8) * 20 + c + 4];
#pragma unroll
                for (int nt = 0; nt < 4; nt++) {
                    int n = wn * 32 + nt * 8 + (lane >> 2);
                    float b0 = Bs[n * 20 + kb + (lane & 3)];
                    float b1 = Bs[n * 20 + kb + 4 + (lane & 3)];
                    mma8(acc[mt][nt], a0, a1, a2, a3, b0, b1);
                }
            }
        }
    }

    // epilogue: relu + NCHW scatter
#pragma unroll
    for (int mt = 0; mt < 2; mt++) {
#pragma unroll
        for (int nt = 0; nt < 4; nt++) {
            int r = m0 + wm * 32 + mt * 16 + (lane >> 2);
            int cc = wn * 32 + nt * 8 + 2 * (lane & 3);
#pragma unroll
            for (int q = 0; q < 4; q++) {
                int rr = r + (q >> 1) * 8;
                int cn = cc + (q & 1);
                float v = fmaxf(acc[mt][nt][q] + bias[cn], 0.f);
                int b = rr / PIX, p = rr % PIX;
                C[((size_t)b * 64 + cn) * PIX + p] = v;
            }
        }
    }
}

// ---------------------------------------------------------------------------
// Generic tf32 GEMM for the FC layers: C[M,N] = A[M,K] * W[N,K]^T + bias
//   M == 128 here (grid.x == 1), Ntot % 64 == 0, K % 16 == 0.
// ---------------------------------------------------------------------------
__global__ void gemm_k(const float* __restrict__ A, int lda,
                       const float* __restrict__ W, int ldw,
                       const float* __restrict__ bias,
                       float* __restrict__ C,
                       int K, int Ntot, int relu) {
    __shared__ float As[128 * 20];
    __shared__ float Bs[64 * 20];

    int tid = threadIdx.x;
    int warp = tid >> 5, lane = tid & 31;
    int wm = warp >> 1;
    int wn = warp & 1;
    int m0 = blockIdx.x * 128;
    int n0 = blockIdx.y * 64;

    float acc[2][4][4];
#pragma unroll
    for (int a = 0; a < 2; a++)
#pragma unroll
        for (int b = 0; b < 4; b++)
#pragma unroll
            for (int c = 0; c < 4; c++) acc[a][b][c] = 0.f;

    for (int k0 = 0; k0 < K; k0 += 16) {
        __syncthreads();
#pragma unroll
        for (int i = 0; i < 8; i++) {
            int e = i * 256 + tid;
            int m = e >> 4, k = e & 15;
            As[m * 20 + k] = tf32f(A[(size_t)(m0 + m) * lda + k0 + k]);
        }
#pragma unroll
        for (int i = 0; i < 4; i++) {
            int e = i * 256 + tid;
            int n = e >> 4, k = e & 15;
            Bs[n * 20 + k] = tf32f(W[(size_t)(n0 + n) * ldw + k0 + k]);
        }
        __syncthreads();

#pragma unroll
        for (int kk = 0; kk < 2; kk++) {
            int kb = kk * 8;
#pragma unroll
            for (int mt = 0; mt < 2; mt++) {
                int r = wm * 32 + mt * 16 + (lane >> 2);
                int c = kb + (lane & 3);
                float a0 = As[r * 20 + c];
                float a1 = As[(r + 8) * 20 + c];
                float a2 = As[r * 20 + c + 4];
                float a3 = As[(r + 8) * 20 + c + 4];
#pragma unroll
                for (int nt = 0; nt < 4; nt++) {
                    int n = wn * 32 + nt * 8 + (lane >> 2);
                    float b0 = Bs[n * 20 + kb + (lane & 3)];
                    float b1 = Bs[n * 20 + kb + 4 + (lane & 3)];
                    mma8(acc[mt][nt], a0, a1, a2, a3, b0, b1);
                }
            }
        }
    }

#pragma unroll
    for (int mt = 0; mt < 2; mt++) {
#pragma unroll
        for (int nt = 0; nt < 4; nt++) {
            int r = m0 + wm * 32 + mt * 16 + (lane >> 2);
            int cc = n0 + wn * 32 + nt * 8 + 2 * (lane & 3);
#pragma unroll
            for (int q = 0; q < 4; q++) {
                int rr = r + (q >> 1) * 8;
                int cn = cc + (q & 1);
                float v = acc[mt][nt][q] + bias[cn];
                if (relu) v = fmaxf(v, 0.f);
                C[(size_t)rr * Ntot + cn] = v;
            }
        }
    }
}

// ---------------------------------------------------------------------------
// gi precompute: gi[t][b][g] = actions[b][t][:] . w_ih[g][:] + b_ih[g]
// ---------------------------------------------------------------------------
__global__ void gi_k(const float* __restrict__ actions,
                     const float* __restrict__ w_ih,
                     const float* __restrict__ b_ih) {
    int idx = blockIdx.x * blockDim.x + threadIdx.x;
    if (idx >= TT * BB * G3) return;
    int g = idx % G3;
    int tb = idx / G3;
    int b = tb % BB, t = tb / BB;
    float a0 = actions[((size_t)b * TT + t) * 2 + 0];
    float a1 = actions[((size_t)b * TT + t) * 2 + 1];
    g_gi[idx] = a0 * w_ih[g * 2] + a1 * w_ih[g * 2 + 1] + b_ih[g];
}

// ---------------------------------------------------------------------------
// Persistent GRU. 128 CTAs x 256 threads. 4 INDEPENDENT groups of 32 CTAs
// (group = batch slice); per-step group barrier via per-CTA padded flags
// (release store + direct poll, no atomics, no cross-group coupling).
// CTA (ib, jg): batch rows [ib*32,+32), hidden cols [jg*16,+16), all 3 gates.
// ---------------------------------------------------------------------------
__global__ void __launch_bounds__(GTH, 1)
gru_k(const float* __restrict__ gi,
      const float* __restrict__ w_hh,
      const float* __restrict__ b_hh,
      float* __restrict__ out,
      float* __restrict__ hT) {
    extern __shared__ float sm[];
    float* Hs = sm;                              // [32][516]
    float* Ws = sm + 32 * HS_STRIDE;             // [48][516]
    float* Gs = Ws + 48 * WS_STRIDE;             // [32][48]

    int tid = threadIdx.x;
    int warp = tid >> 5, lane = tid & 31;
    int wm = warp & 1;
    int wn = warp >> 1;
    int nsub = (wn < 2) ? 2 : 1;
    int sub0 = (wn < 2) ? wn * 2 : wn + 2;

    int cta = blockIdx.x;
    int ib = cta >> 5;
    int jg = cta & 31;
    int j0 = jg * GJT;

    // flag base (all flags equal at kernel entry; each CTA bumps its own
    // flag exactly TT-1 times per launch, so equality is preserved)
    unsigned fbase = *(volatile unsigned*)&g_flag[ib][jg][0];

    // per-thread gate-fusion constants (2 elements per thread)
    int e0 = tid, e1 = tid + GTH;
    int bl0 = e0 >> 4, jj0 = e0 & 15, bg0 = ib * 32 + bl0, jA = j0 + jj0;
    int bl1 = e1 >> 4, jj1 = e1 & 15, bg1 = ib * 32 + bl1, jB = j0 + jj1;
    float bhr0 = b_hh[jA], bhi0 = b_hh[512 + jA], bhn0 = b_hh[1024 + jA];
    float bhr1 = b_hh[jB], bhi1 = b_hh[512 + jB], bhn1 = b_hh[1024 + jB];

    // Load w_hh slice once: rows {j0..j0+15} of gates r,i,n (48 x 512), RNA tf32
    for (int e = tid; e < 48 * 512; e += GTH) {
        int rr = e >> 9, k = e & 511;
        int gate = rr >> 4, jj = rr & 15;
        Ws[rr * WS_STRIDE + k] =
            tf32f(w_hh[((size_t)gate * 512 + j0 + jj) * 512 + k]);
    }

    for (int t = 0; t < TT; t++) {
        const float* hcur = g_h[t & 1];
        float* hnxt = g_h[(t + 1) & 1];

        // prefetch gi (DRAM) and own h values (L2) for the gate phase
        const float* g0 = gi + ((size_t)t * BB + bg0) * G3;
        const float* g1 = gi + ((size_t)t * BB + bg1) * G3;
        float gr0 = __ldg(g0 + jA), gz0 = __ldg(g0 + 512 + jA), gn0 = __ldg(g0 + 1024 + jA);
        float gr1 = __ldg(g1 + jB), gz1 = __ldg(g1 + 512 + jB), gn1 = __ldg(g1 + 1024 + jB);
        float hv0 = __ldcg(hcur + (size_t)bg0 * HIDN + jA);
        float hv1 = __ldcg(hcur + (size_t)bg1 * HIDN + jB);

        // stage h tile into smem via cp.async (L2-only, no L1 staleness)
        {
            const char* hsrc = (const char*)(hcur + (size_t)ib * 32 * HIDN);
#pragma unroll
            for (int i = 0; i < 16; i++) {
                int e = i * GTH + tid;
                int r = e >> 7, c4 = e & 127;
                unsigned dst = (unsigned)__cvta_generic_to_shared(
                    Hs + r * HS_STRIDE + c4 * 4);
                const char* s = hsrc + ((size_t)r * HIDN + c4 * 4) * 4;
                asm volatile("cp.async.cg.shared.global [%0], [%1], 16;\n"
                             :: "r"(dst), "l"(s));
            }
            asm volatile("cp.async.commit_group;\n");
            asm volatile("cp.async.wait_group 0;\n");
        }
        __syncthreads();

        float acc[2][4];
#pragma unroll
        for (int a = 0; a < 2; a++)
#pragma unroll
            for (int c = 0; c < 4; c++) acc[a][c] = 0.f;

#pragma unroll 4
        for (int k8 = 0; k8 < 64; k8++) {
            int kb = k8 * 8;
            int r = wm * 16 + (lane >> 2);
            int c = kb + (lane & 3);
            float a0 = Hs[r * HS_STRIDE + c];
            float a1 = Hs[(r + 8) * HS_STRIDE + c];
            float a2 = Hs[r * HS_STRIDE + c + 4];
            float a3 = Hs[(r + 8) * HS_STRIDE + c + 4];
#pragma unroll
            for (int i = 0; i < 2; i++) {
                if (i < nsub) {
                    int n = (sub0 + i) * 8 + (lane >> 2);
                    float b0 = Ws[n * WS_STRIDE + kb + (lane & 3)];
                    float b1 = Ws[n * WS_STRIDE + kb + 4 + (lane & 3)];
                    mma8(acc[i], a0, a1, a2, a3, b0, b1);
                }
            }
        }

        // dump gh fragments for gate fusion
#pragma unroll
        for (int i = 0; i < 2; i++) {
            if (i < nsub) {
                int s = sub0 + i;
                int r = wm * 16 + (lane >> 2);
                int c = s * 8 + 2 * (lane & 3);
                Gs[r * 48 + c]           = acc[i][0];
                Gs[r * 48 + c + 1]       = acc[i][1];
                Gs[(r + 8) * 48 + c]     = acc[i][2];
                Gs[(r + 8) * 48 + c + 1] = acc[i][3];
            }
        }
        __syncthreads();

        // fused gates (exact f32 state update), 2 elements per thread
        {
            float ghr = Gs[bl0 * 48 + jj0]      + bhr0;
            float ghi = Gs[bl0 * 48 + 16 + jj0] + bhi0;
            float ghn = Gs[bl0 * 48 + 32 + jj0] + bhn0;
            float r = 1.f / (1.f + expf(-(gr0 + ghr)));
            float z = 1.f / (1.f + expf(-(gz0 + ghi)));
            float n = tanhf(gn0 + r * ghn);
            float hy = n + z * (hv0 - n);
            hnxt[(size_t)bg0 * HIDN + jA] = hy;
            out[((size_t)bg0 * TT + t) * HIDN + jA] = hy;
            if (t == TT - 1) hT[(size_t)bg0 * HIDN + jA] = hy;
        }
        {
            float ghr = Gs[bl1 * 48 + jj1]      + bhr1;
            float ghi = Gs[bl1 * 48 + 16 + jj1] + bhi1;
            float ghn = Gs[bl1 * 48 + 32 + jj1] + bhn1;
            float r = 1.f / (1.f + expf(-(gr1 + ghr)));
            float z = 1.f / (1.f + expf(-(gz1 + ghi)));
            float n = tanhf(gn1 + r * ghn);
            float hy = n + z * (hv1 - n);
            hnxt[(size_t)bg1 * HIDN + jB] = hy;
            out[((size_t)bg1 * TT + t) * HIDN + jB] = hy;
            if (t == TT - 1) hT[(size_t)bg1 * HIDN + jB] = hy;
        }

        // group barrier (32 CTAs of this ib group); skip after last step
        if (t < TT - 1) {
            __threadfence();
            __syncthreads();
            if (tid == 0)
                *(volatile unsigned*)&g_flag[ib][jg][0] = fbase + (unsigned)(t + 1);
            if (tid < 32) {
                while ((*(volatile unsigned*)&g_flag[ib][tid][0] - fbase)
                       < (unsigned)(t + 1)) { }
            }
            __syncthreads();
        }
    }
}

// ---------------------------------------------------------------------------
// Host launch
// ---------------------------------------------------------------------------
extern "C" void kernel_launch(void* const* d_in, const int* in_sizes, int n_in,
                              void* d_out, int out_size) {
    const float* images  = (const float*)d_in[0];
    const float* actions = (const float*)d_in[1];
    const float* cw1 = (const float*)d_in[2];
    const float* cb1 = (const float*)d_in[3];
    const float* cw2 = (const float*)d_in[4];
    const float* cb2 = (const float*)d_in[5];
    const float* cw3 = (const float*)d_in[6];
    const float* cb3 = (const float*)d_in[7];
    const float* fw1 = (const float*)d_in[8];
    const float* fb1 = (const float*)d_in[9];
    const float* fw2 = (const float*)d_in[10];
    const float* fb2 = (const float*)d_in[11];
    const float* fw3 = (const float*)d_in[12];
    const float* fb3 = (const float*)d_in[13];
    const float* w_ih = (const float*)d_in[14];
    const float* w_hh = (const float*)d_in[15];
    const float* b_ih = (const float*)d_in[16];
    const float* b_hh = (const float*)d_in[17];

    float *x1, *x2, *flat, *fc1, *fc2, *hbuf, *gi;
    cudaGetSymbolAddress((void**)&x1,   g_x1);
    cudaGetSymbolAddress((void**)&x2,   g_x2);
    cudaGetSymbolAddress((void**)&flat, g_flat);
    cudaGetSymbolAddress((void**)&fc1,  g_fc1);
    cudaGetSymbolAddress((void**)&fc2,  g_fc2);
    cudaGetSymbolAddress((void**)&hbuf, g_h);
    cudaGetSymbolAddress((void**)&gi,   g_gi);

    const int gru_smem = (32 * HS_STRIDE + 48 * WS_STRIDE + 32 * 48) * 4;
    cudaFuncSetAttribute(gru_k, cudaFuncAttributeMaxDynamicSharedMemorySize,
                         gru_smem);

    // GRU input projections (independent — launch first)
    gi_k<<<(TT * BB * G3 + 255) / 256, 256>>>(actions, w_ih, b_ih);

    // encoder: fused im2col+GEMM convs
    convgemm_k<80, 75, 3, 72, 5, 24><<<576, 256>>>(images, cw1, cb1, x1);
    convgemm_k<576, 576, 64, 24, 3, 9><<<81, 256>>>(x1, cw2, cb2, x2);
    convgemm_k<576, 576, 64, 9, 3, 4><<<16, 256>>>(x2, cw3, cb3, flat);

    // FC head
    gemm_k<<<dim3(1, 16), 256>>>(flat, 1024, fw1, 1024, fb1, fc1, 1024, 1024, 1);
    gemm_k<<<dim3(1, 8), 256>>>(fc1, 1024, fw2, 1024, fb2, fc2, 1024, 512, 1);
    gemm_k<<<dim3(1, 8), 256>>>(fc2, 512, fw3, 512, fb3, hbuf, 512, 512, 0);

    // persistent GRU
    float* out = (float*)d_out;
    float* hT = out + (size_t)BB * TT * HIDN;
    gru_k<<<GNC, GTH, gru_smem>>>(gi, w_hh, b_hh, out, hT);
}

// round 5
// speedup vs baseline: 1.4678x; 1.0076x over previous
#include <cuda_runtime.h>
#include <cstdint>
#include <math.h>

// ---------------------------------------------------------------------------
// Problem constants
// ---------------------------------------------------------------------------
#define BB   128
#define TT   100
#define HIDN 512
#define G3   1536

// GRU tiling
#define GMB  32       // batch tile
#define GJT  16       // hidden-col tile
#define GNC  128      // CTAs = (128/32)*(512/16)
#define GTH  256      // threads (8 warps)
#define HS_STRIDE 516
#define WS_STRIDE 516

// ---------------------------------------------------------------------------
// Device scratch (no allocations allowed -> __device__ globals)
// ---------------------------------------------------------------------------
__device__ float g_x1  [(size_t)BB * 64 * 576];   // conv1 out, NCHW
__device__ float g_x2  [(size_t)BB * 64 * 81];    // conv2 out, NCHW
__device__ float g_flat[(size_t)BB * 1024];       // conv3 out == flatten
__device__ float g_fc1 [(size_t)BB * 1024];
__device__ float g_fc2 [(size_t)BB * 512];
__device__ __align__(16) float g_h[2][(size_t)BB * HIDN];
__device__ float g_gi  [(size_t)TT * BB * G3];
__device__ unsigned g_flag[4][32][32];            // [group][cta][pad to 128B]

// ---------------------------------------------------------------------------
// Helpers
// ---------------------------------------------------------------------------
__device__ __forceinline__ float tf32f(float x) {
    unsigned u;
    asm("cvt.rna.tf32.f32 %0, %1;" : "=r"(u) : "f"(x));
    return __uint_as_float(u);
}

__device__ __forceinline__ void mma8(float* c,
                                     float a0, float a1, float a2, float a3,
                                     float b0, float b1) {
    unsigned A0 = __float_as_uint(a0), A1 = __float_as_uint(a1);
    unsigned A2 = __float_as_uint(a2), A3 = __float_as_uint(a3);
    unsigned B0 = __float_as_uint(b0), B1 = __float_as_uint(b1);
    asm volatile(
        "mma.sync.aligned.m16n8k8.row.col.f32.tf32.tf32.f32 "
        "{%0,%1,%2,%3}, {%4,%5,%6,%7}, {%8,%9}, {%0,%1,%2,%3};"
        : "+f"(c[0]), "+f"(c[1]), "+f"(c[2]), "+f"(c[3])
        : "r"(A0), "r"(A1), "r"(A2), "r"(A3), "r"(B0), "r"(B1));
}

// ---------------------------------------------------------------------------
// Fused im2col + tf32 GEMM conv:  out[b, oc, p] = relu(conv(src) + bias)
//   src NCHW [B, CIN, IH, IH]; W [64, KW] row-major (KW = CIN*KS*KS);
//   stride 3, pad 2.  Ntot = 64 (single n-block).  M = B*OW*OW, tiled by 128.
// ---------------------------------------------------------------------------
template<int KTOT, int KW, int CIN, int IH, int KS, int OW>
__global__ void convgemm_k(const float* __restrict__ src,
                           const float* __restrict__ W,
                           const float* __restrict__ bias,
                           float* __restrict__ C) {
    constexpr int PIX = OW * OW;
    __shared__ float As[128 * 20];
    __shared__ float Bs[64 * 20];

    int tid = threadIdx.x;
    int warp = tid >> 5, lane = tid & 31;
    int wm = warp >> 1;        // 0..3 : 32 rows each
    int wn = warp & 1;         // 0..1 : 32 cols each
    int m0 = blockIdx.x * 128;

    float acc[2][4][4];
#pragma unroll
    for (int a = 0; a < 2; a++)
#pragma unroll
        for (int b = 0; b < 4; b++)
#pragma unroll
            for (int c = 0; c < 4; c++) acc[a][b][c] = 0.f;

    for (int k0 = 0; k0 < KTOT; k0 += 16) {
        __syncthreads();
        // A tile 128x16: im2col on the fly
        {
            int kk = tid & 15;
            int k = k0 + kk;
            int ci = 0, ky = 0, kx = 0;
            bool kok = (k < KW);
            if (kok) {
                ci = k / (KS * KS);
                int rem = k % (KS * KS);
                ky = rem / KS; kx = rem % KS;
            }
#pragma unroll
            for (int i = 0; i < 8; i++) {
                int mloc = i * 16 + (tid >> 4);
                int m = m0 + mloc;
                float v = 0.f;
                if (kok) {
                    int b = m / PIX, pix = m % PIX;
                    int oy = pix / OW, ox = pix % OW;
                    int iy = oy * 3 - 2 + ky;
                    int ix = ox * 3 - 2 + kx;
                    if (iy >= 0 && iy < IH && ix >= 0 && ix < IH)
                        v = src[((size_t)(b * CIN + ci) * IH + iy) * IH + ix];
                }
                As[mloc * 20 + kk] = tf32f(v);
            }
        }
        // W tile 64x16
#pragma unroll
        for (int i = 0; i < 4; i++) {
            int e = i * 256 + tid;
            int n = e >> 4, k = e & 15;
            float v = (k0 + k < KW) ? W[(size_t)n * KW + k0 + k] : 0.f;
            Bs[n * 20 + k] = tf32f(v);
        }
        __syncthreads();

#pragma unroll
        for (int kk = 0; kk < 2; kk++) {
            int kb = kk * 8;
#pragma unroll
            for (int mt = 0; mt < 2; mt++) {
                int r = wm * 32 + mt * 16 + (lane >> 2);
                int c = kb + (lane & 3);
                float a0 = As[r * 20 + c];
                float a1 = As[(r + 8) * 20 + c];
                float a2 = As[r * 20 + c + 4];
                float a3 = As[(r + 8) * 20 + c + 4];
#pragma unroll
                for (int nt = 0; nt < 4; nt++) {
                    int n = wn * 32 + nt * 8 + (lane >> 2);
                    float b0 = Bs[n * 20 + kb + (lane & 3)];
                    float b1 = Bs[n * 20 + kb + 4 + (lane & 3)];
                    mma8(acc[mt][nt], a0, a1, a2, a3, b0, b1);
                }
            }
        }
    }

    // epilogue: relu + NCHW scatter
#pragma unroll
    for (int mt = 0; mt < 2; mt++) {
#pragma unroll
        for (int nt = 0; nt < 4; nt++) {
            int r = m0 + wm * 32 + mt * 16 + (lane >> 2);
            int cc = wn * 32 + nt * 8 + 2 * (lane & 3);
#pragma unroll
            for (int q = 0; q < 4; q++) {
                int rr = r + (q >> 1) * 8;
                int cn = cc + (q & 1);
                float v = fmaxf(acc[mt][nt][q] + bias[cn], 0.f);
                int b = rr / PIX, p = rr % PIX;
                C[((size_t)b * 64 + cn) * PIX + p] = v;
            }
        }
    }
}

// ---------------------------------------------------------------------------
// Generic tf32 GEMM for the FC layers: C[M,N] = A[M,K] * W[N,K]^T + bias
//   M == 128 here (grid.x == 1), Ntot % 64 == 0, K % 16 == 0.
// ---------------------------------------------------------------------------
__global__ void gemm_k(const float* __restrict__ A, int lda,
                       const float* __restrict__ W, int ldw,
                       const float* __restrict__ bias,
                       float* __restrict__ C,
                       int K, int Ntot, int relu) {
    __shared__ float As[128 * 20];
    __shared__ float Bs[64 * 20];

    int tid = threadIdx.x;
    int warp = tid >> 5, lane = tid & 31;
    int wm = warp >> 1;
    int wn = warp & 1;
    int m0 = blockIdx.x * 128;
    int n0 = blockIdx.y * 64;

    float acc[2][4][4];
#pragma unroll
    for (int a = 0; a < 2; a++)
#pragma unroll
        for (int b = 0; b < 4; b++)
#pragma unroll
            for (int c = 0; c < 4; c++) acc[a][b][c] = 0.f;

    for (int k0 = 0; k0 < K; k0 += 16) {
        __syncthreads();
#pragma unroll
        for (int i = 0; i < 8; i++) {
            int e = i * 256 + tid;
            int m = e >> 4, k = e & 15;
            As[m * 20 + k] = tf32f(A[(size_t)(m0 + m) * lda + k0 + k]);
        }
#pragma unroll
        for (int i = 0; i < 4; i++) {
            int e = i * 256 + tid;
            int n = e >> 4, k = e & 15;
            Bs[n * 20 + k] = tf32f(W[(size_t)(n0 + n) * ldw + k0 + k]);
        }
        __syncthreads();

#pragma unroll
        for (int kk = 0; kk < 2; kk++) {
            int kb = kk * 8;
#pragma unroll
            for (int mt = 0; mt < 2; mt++) {
                int r = wm * 32 + mt * 16 + (lane >> 2);
                int c = kb + (lane & 3);
                float a0 = As[r * 20 + c];
                float a1 = As[(r + 8) * 20 + c];
                float a2 = As[r * 20 + c + 4];
                float a3 = As[(r + 8) * 20 + c + 4];
#pragma unroll
                for (int nt = 0; nt < 4; nt++) {
                    int n = wn * 32 + nt * 8 + (lane >> 2);
                    float b0 = Bs[n * 20 + kb + (lane & 3)];
                    float b1 = Bs[n * 20 + kb + 4 + (lane & 3)];
                    mma8(acc[mt][nt], a0, a1, a2, a3, b0, b1);
                }
            }
        }
    }

#pragma unroll
    for (int mt = 0; mt < 2; mt++) {
#pragma unroll
        for (int nt = 0; nt < 4; nt++) {
            int r = m0 + wm * 32 + mt * 16 + (lane >> 2);
            int cc = n0 + wn * 32 + nt * 8 + 2 * (lane & 3);
#pragma unroll
            for (int q = 0; q < 4; q++) {
                int rr = r + (q >> 1) * 8;
                int cn = cc + (q & 1);
                float v = acc[mt][nt][q] + bias[cn];
                if (relu) v = fmaxf(v, 0.f);
                C[(size_t)rr * Ntot + cn] = v;
            }
        }
    }
}

// ---------------------------------------------------------------------------
// gi precompute: gi[t][b][g] = actions[b][t][:] . w_ih[g][:] + b_ih[g]
// ---------------------------------------------------------------------------
__global__ void gi_k(const float* __restrict__ actions,
                     const float* __restrict__ w_ih,
                     const float* __restrict__ b_ih) {
    int idx = blockIdx.x * blockDim.x + threadIdx.x;
    if (idx >= TT * BB * G3) return;
    int g = idx % G3;
    int tb = idx / G3;
    int b = tb % BB, t = tb / BB;
    float a0 = actions[((size_t)b * TT + t) * 2 + 0];
    float a1 = actions[((size_t)b * TT + t) * 2 + 1];
    g_gi[idx] = a0 * w_ih[g * 2] + a1 * w_ih[g * 2 + 1] + b_ih[g];
}

// ---------------------------------------------------------------------------
// Persistent GRU. 128 CTAs x 256 threads. 4 INDEPENDENT groups of 32 CTAs
// (group = batch slice); per-step group barrier via per-CTA padded flags
// (release store + direct poll, no atomics, no cross-group coupling).
// CTA (ib, jg): batch rows [ib*32,+32), hidden cols [jg*16,+16), all 3 gates.
// ---------------------------------------------------------------------------
__global__ void __launch_bounds__(GTH, 1)
gru_k(const float* __restrict__ gi,
      const float* __restrict__ w_hh,
      const float* __restrict__ b_hh,
      float* __restrict__ out,
      float* __restrict__ hT) {
    extern __shared__ float sm[];
    float* Hs = sm;                              // [32][516]
    float* Ws = sm + 32 * HS_STRIDE;             // [48][516]
    float* Gs = Ws + 48 * WS_STRIDE;             // [32][48]

    int tid = threadIdx.x;
    int warp = tid >> 5, lane = tid & 31;
    int wm = warp & 1;
    int wn = warp >> 1;
    int nsub = (wn < 2) ? 2 : 1;
    int sub0 = (wn < 2) ? wn * 2 : wn + 2;

    int cta = blockIdx.x;
    int ib = cta >> 5;
    int jg = cta & 31;
    int j0 = jg * GJT;

    // flag base (all flags equal at kernel entry; each CTA bumps its own
    // flag exactly TT-1 times per launch, so equality is preserved)
    unsigned fbase = *(volatile unsigned*)&g_flag[ib][jg][0];

    // per-thread gate-fusion constants (2 elements per thread)
    int e0 = tid, e1 = tid + GTH;
    int bl0 = e0 >> 4, jj0 = e0 & 15, bg0 = ib * 32 + bl0, jA = j0 + jj0;
    int bl1 = e1 >> 4, jj1 = e1 & 15, bg1 = ib * 32 + bl1, jB = j0 + jj1;
    float bhr0 = b_hh[jA], bhi0 = b_hh[512 + jA], bhn0 = b_hh[1024 + jA];
    float bhr1 = b_hh[jB], bhi1 = b_hh[512 + jB], bhn1 = b_hh[1024 + jB];

    // Load w_hh slice once: rows {j0..j0+15} of gates r,i,n (48 x 512), RNA tf32
    for (int e = tid; e < 48 * 512; e += GTH) {
        int rr = e >> 9, k = e & 511;
        int gate = rr >> 4, jj = rr & 15;
        Ws[rr * WS_STRIDE + k] =
            tf32f(w_hh[((size_t)gate * 512 + j0 + jj) * 512 + k]);
    }

    for (int t = 0; t < TT; t++) {
        const float* hcur = g_h[t & 1];
        float* hnxt = g_h[(t + 1) & 1];

        // prefetch gi (DRAM) and own h values (L2) for the gate phase
        const float* g0 = gi + ((size_t)t * BB + bg0) * G3;
        const float* g1 = gi + ((size_t)t * BB + bg1) * G3;
        float gr0 = __ldg(g0 + jA), gz0 = __ldg(g0 + 512 + jA), gn0 = __ldg(g0 + 1024 + jA);
        float gr1 = __ldg(g1 + jB), gz1 = __ldg(g1 + 512 + jB), gn1 = __ldg(g1 + 1024 + jB);
        float hv0 = __ldcg(hcur + (size_t)bg0 * HIDN + jA);
        float hv1 = __ldcg(hcur + (size_t)bg1 * HIDN + jB);

        // stage h tile into smem via cp.async (L2-only, no L1 staleness)
        {
            const char* hsrc = (const char*)(hcur + (size_t)ib * 32 * HIDN);
#pragma unroll
            for (int i = 0; i < 16; i++) {
                int e = i * GTH + tid;
                int r = e >> 7, c4 = e & 127;
                unsigned dst = (unsigned)__cvta_generic_to_shared(
                    Hs + r * HS_STRIDE + c4 * 4);
                const char* s = hsrc + ((size_t)r * HIDN + c4 * 4) * 4;
                asm volatile("cp.async.cg.shared.global [%0], [%1], 16;\n"
                             :: "r"(dst), "l"(s));
            }
            asm volatile("cp.async.commit_group;\n");
            asm volatile("cp.async.wait_group 0;\n");
        }
        __syncthreads();

        float acc[2][4];
#pragma unroll
        for (int a = 0; a < 2; a++)
#pragma unroll
            for (int c = 0; c < 4; c++) acc[a][c] = 0.f;

#pragma unroll 4
        for (int k8 = 0; k8 < 64; k8++) {
            int kb = k8 * 8;
            int r = wm * 16 + (lane >> 2);
            int c = kb + (lane & 3);
            float a0 = Hs[r * HS_STRIDE + c];
            float a1 = Hs[(r + 8) * HS_STRIDE + c];
            float a2 = Hs[r * HS_STRIDE + c + 4];
            float a3 = Hs[(r + 8) * HS_STRIDE + c + 4];
#pragma unroll
            for (int i = 0; i < 2; i++) {
                if (i < nsub) {
                    int n = (sub0 + i) * 8 + (lane >> 2);
                    float b0 = Ws[n * WS_STRIDE + kb + (lane & 3)];
                    float b1 = Ws[n * WS_STRIDE + kb + 4 + (lane & 3)];
                    mma8(acc[i], a0, a1, a2, a3, b0, b1);
                }
            }
        }

        // dump gh fragments for gate fusion
#pragma unroll
        for (int i = 0; i < 2; i++) {
            if (i < nsub) {
                int s = sub0 + i;
                int r = wm * 16 + (lane >> 2);
                int c = s * 8 + 2 * (lane & 3);
                Gs[r * 48 + c]           = acc[i][0];
                Gs[r * 48 + c + 1]       = acc[i][1];
                Gs[(r + 8) * 48 + c]     = acc[i][2];
                Gs[(r + 8) * 48 + c + 1] = acc[i][3];
            }
        }
        __syncthreads();

        // fused gates (exact f32 state update), 2 elements per thread
        {
            float ghr = Gs[bl0 * 48 + jj0]      + bhr0;
            float ghi = Gs[bl0 * 48 + 16 + jj0] + bhi0;
            float ghn = Gs[bl0 * 48 + 32 + jj0] + bhn0;
            float r = 1.f / (1.f + expf(-(gr0 + ghr)));
            float z = 1.f / (1.f + expf(-(gz0 + ghi)));
            float n = tanhf(gn0 + r * ghn);
            float hy = n + z * (hv0 - n);
            hnxt[(size_t)bg0 * HIDN + jA] = hy;
            out[((size_t)bg0 * TT + t) * HIDN + jA] = hy;
            if (t == TT - 1) hT[(size_t)bg0 * HIDN + jA] = hy;
        }
        {
            float ghr = Gs[bl1 * 48 + jj1]      + bhr1;
            float ghi = Gs[bl1 * 48 + 16 + jj1] + bhi1;
            float ghn = Gs[bl1 * 48 + 32 + jj1] + bhn1;
            float r = 1.f / (1.f + expf(-(gr1 + ghr)));
            float z = 1.f / (1.f + expf(-(gz1 + ghi)));
            float n = tanhf(gn1 + r * ghn);
            float hy = n + z * (hv1 - n);
            hnxt[(size_t)bg1 * HIDN + jB] = hy;
            out[((size_t)bg1 * TT + t) * HIDN + jB] = hy;
            if (t == TT - 1) hT[(size_t)bg1 * HIDN + jB] = hy;
        }

        // group barrier (32 CTAs of this ib group); skip after last step
        if (t < TT - 1) {
            __threadfence();
            __syncthreads();
            if (tid == 0)
                *(volatile unsigned*)&g_flag[ib][jg][0] = fbase + (unsigned)(t + 1);
            if (tid < 32) {
                while ((*(volatile unsigned*)&g_flag[ib][tid][0] - fbase)
                       < (unsigned)(t + 1)) { }
            }
            __syncthreads();
        }
    }
}

// ---------------------------------------------------------------------------
// Host launch
// ---------------------------------------------------------------------------
extern "C" void kernel_launch(void* const* d_in, const int* in_sizes, int n_in,
                              void* d_out, int out_size) {
    const float* images  = (const float*)d_in[0];
    const float* actions = (const float*)d_in[1];
    const float* cw1 = (const float*)d_in[2];
    const float* cb1 = (const float*)d_in[3];
    const float* cw2 = (const float*)d_in[4];
    const float* cb2 = (const float*)d_in[5];
    const float* cw3 = (const float*)d_in[6];
    const float* cb3 = (const float*)d_in[7];
    const float* fw1 = (const float*)d_in[8];
    const float* fb1 = (const float*)d_in[9];
    const float* fw2 = (const float*)d_in[10];
    const float* fb2 = (const float*)d_in[11];
    const float* fw3 = (const float*)d_in[12];
    const float* fb3 = (const float*)d_in[13];
    const float* w_ih = (const float*)d_in[14];
    const float* w_hh = (const float*)d_in[15];
    const float* b_ih = (const float*)d_in[16];
    const float* b_hh = (const float*)d_in[17];

    float *x1, *x2, *flat, *fc1, *fc2, *hbuf, *gi;
    cudaGetSymbolAddress((void**)&x1,   g_x1);
    cudaGetSymbolAddress((void**)&x2,   g_x2);
    cudaGetSymbolAddress((void**)&flat, g_flat);
    cudaGetSymbolAddress((void**)&fc1,  g_fc1);
    cudaGetSymbolAddress((void**)&fc2,  g_fc2);
    cudaGetSymbolAddress((void**)&hbuf, g_h);
    cudaGetSymbolAddress((void**)&gi,   g_gi);

    const int gru_smem = (32 * HS_STRIDE + 48 * WS_STRIDE + 32 * 48) * 4;
    cudaFuncSetAttribute(gru_k, cudaFuncAttributeMaxDynamicSharedMemorySize,
                         gru_smem);

    // GRU input projections (independent — launch first)
    gi_k<<<(TT * BB * G3 + 255) / 256, 256>>>(actions, w_ih, b_ih);

    // encoder: fused im2col+GEMM convs
    convgemm_k<80, 75, 3, 72, 5, 24><<<576, 256>>>(images, cw1, cb1, x1);
    convgemm_k<576, 576, 64, 24, 3, 9><<<81, 256>>>(x1, cw2, cb2, x2);
    convgemm_k<576, 576, 64, 9, 3, 4><<<16, 256>>>(x2, cw3, cb3, flat);

    // FC head
    gemm_k<<<dim3(1, 16), 256>>>(flat, 1024, fw1, 1024, fb1, fc1, 1024, 1024, 1);
    gemm_k<<<dim3(1, 8), 256>>>(fc1, 1024, fw2, 1024, fb2, fc2, 1024, 512, 1);
    gemm_k<<<dim3(1, 8), 256>>>(fc2, 512, fw3, 512, fb3, hbuf, 512, 512, 0);

    // persistent GRU
    float* out = (float*)d_out;
    float* hT = out + (size_t)BB * TT * HIDN;
    gru_k<<<GNC, GTH, gru_smem>>>(gi, w_hh, b_hh, out, hT);
}